// round 14
// baseline (speedup 1.0000x reference)
#include <cuda_runtime.h>
#include <cuda_bf16.h>
#include <cstdint>

// Problem constants
#define BB 4
#define S1C 2048
#define S2C 2048
#define NH 8
#define MROWS (BB * S1C)    // 8192
#define ND 512
#define KD 512

// Scratch (device globals — no allocation allowed)
__device__ __align__(16) float g_Q [MROWS * ND];
__device__ __align__(16) float g_K [MROWS * ND];
__device__ __align__(16) float g_V [MROWS * ND];   // holds V^T: [B*512+col][2048]
__device__ __align__(16) __nv_bfloat16 g_Xh[3 * (size_t)MROWS * ND];
__device__ __align__(16) __nv_bfloat16 g_Xl[3 * (size_t)MROWS * ND];
__device__ __align__(16) __nv_bfloat16 g_ATTh[(size_t)MROWS * ND];
__device__ __align__(16) __nv_bfloat16 g_ATTl[(size_t)MROWS * ND];
__device__ __align__(16) __nv_bfloat16 g_WTh[4 * (size_t)KD * ND];  // W^T [n][k] hi
__device__ __align__(16) __nv_bfloat16 g_WTl[4 * (size_t)KD * ND];  // W^T [n][k] lo

// ---------------------------------------------------------------------------
// helpers
// ---------------------------------------------------------------------------
__device__ __forceinline__ uint32_t smem_u32(const void* p) {
    uint32_t a;
    asm("{ .reg .u64 t; cvta.to.shared.u64 t, %1; cvt.u32.u64 %0, t; }"
        : "=r"(a) : "l"(p));
    return a;
}

__device__ __forceinline__ void cp16(uint32_t dst, const void* src) {
    asm volatile("cp.async.cg.shared.global [%0], [%1], 16;"
                 :: "r"(dst), "l"(src) : "memory");
}
#define CP_COMMIT() asm volatile("cp.async.commit_group;" ::: "memory")
#define CP_WAIT0()  asm volatile("cp.async.wait_group 0;" ::: "memory")
#define CP_WAIT1()  asm volatile("cp.async.wait_group 1;" ::: "memory")

__device__ __forceinline__ float to_tf32(float x) {
    float y;
    asm("cvt.rna.tf32.f32 %0, %1;" : "=f"(y) : "f"(x));
    return y;
}

__device__ __forceinline__ void mma_bf16(float* c, const uint32_t* a, const uint32_t* b) {
    asm volatile(
        "mma.sync.aligned.m16n8k16.row.col.f32.bf16.bf16.f32 "
        "{%0,%1,%2,%3}, {%4,%5,%6,%7}, {%8,%9}, {%0,%1,%2,%3};"
        : "+f"(c[0]), "+f"(c[1]), "+f"(c[2]), "+f"(c[3])
        : "r"(a[0]), "r"(a[1]), "r"(a[2]), "r"(a[3]), "r"(b[0]), "r"(b[1]));
}

__device__ __forceinline__ void mma_tf32(float* c, const uint32_t* a, const uint32_t* b) {
    asm volatile(
        "mma.sync.aligned.m16n8k8.row.col.f32.tf32.tf32.f32 "
        "{%0,%1,%2,%3}, {%4,%5,%6,%7}, {%8,%9}, {%0,%1,%2,%3};"
        : "+f"(c[0]), "+f"(c[1]), "+f"(c[2]), "+f"(c[3])
        : "r"(a[0]), "r"(a[1]), "r"(a[2]), "r"(a[3]), "r"(b[0]), "r"(b[1]));
}

__device__ __forceinline__ uint32_t pack2(__nv_bfloat16 a, __nv_bfloat16 b) {
    return (uint32_t)__bfloat16_as_ushort(a) | ((uint32_t)__bfloat16_as_ushort(b) << 16);
}

__device__ __forceinline__ void split2(float x, float y, uint32_t& hi, uint32_t& lo) {
    __nv_bfloat16 h0 = __float2bfloat16(x), h1 = __float2bfloat16(y);
    hi = pack2(h0, h1);
    lo = pack2(__float2bfloat16(x - __bfloat162float(h0)),
               __float2bfloat16(y - __bfloat162float(h1)));
}

// ---------------------------------------------------------------------------
// prep_w: W[k][n] -> W^T [n][k-permuted] bf16 hi/lo (Wq scaled by 1/8).
// k-permutation within each 16-block: pair order [0,4,1,5,2,6,3,7].
// ---------------------------------------------------------------------------
__global__ __launch_bounds__(256)
void prep_w(const float* __restrict__ Wq, const float* __restrict__ Wk,
            const float* __restrict__ Wv, const float* __restrict__ Wo)
{
    __shared__ float tbuf[32][33];
    const int z = blockIdx.z;
    const float* W = (z == 0) ? Wq : (z == 1) ? Wk : (z == 2) ? Wv : Wo;
    const float scale = (z == 0) ? 0.125f : 1.0f;
    __nv_bfloat16* oh = g_WTh + (size_t)z * KD * ND;
    __nv_bfloat16* ol = g_WTl + (size_t)z * KD * ND;
    const int k0 = blockIdx.x * 32, n0 = blockIdx.y * 32;
    const int lane = threadIdx.x & 31, r = threadIdx.x >> 5;

#pragma unroll
    for (int i = 0; i < 4; i++) {
        const int row = r + i * 8;
        tbuf[row][lane] = W[(size_t)(k0 + row) * ND + n0 + lane];
    }
    __syncthreads();
    const int kst = k0 + (lane & 16) + 4 * ((lane >> 1) & 3)
                  + 2 * ((lane >> 3) & 1) + (lane & 1);
#pragma unroll
    for (int i = 0; i < 4; i++) {
        const int row = r + i * 8;
        const float x = tbuf[lane][row] * scale;
        const __nv_bfloat16 hb = __float2bfloat16(x);
        oh[(size_t)(n0 + row) * KD + kst] = hb;
        ol[(size_t)(n0 + row) * KD + kst] =
            __float2bfloat16(x - __bfloat162float(hb));
    }
}

// ---------------------------------------------------------------------------
// prep_x: split x (fp32) -> bf16 hi/lo with k-pair permutation.
// ---------------------------------------------------------------------------
__global__ __launch_bounds__(256)
void prep_x(const float* __restrict__ x1, const float* __restrict__ x2,
            const float* __restrict__ x3)
{
    const int z = blockIdx.y;
    const float* x = (z == 0) ? x1 : (z == 1) ? x2 : x3;
    __nv_bfloat16* oh = g_Xh + (size_t)z * MROWS * ND;
    __nv_bfloat16* ol = g_Xl + (size_t)z * MROWS * ND;
    const size_t idx = ((size_t)blockIdx.x * 256 + threadIdx.x) * 16;
    float4 v0 = *(const float4*)&x[idx];
    float4 v1 = *(const float4*)&x[idx + 4];
    float4 v2 = *(const float4*)&x[idx + 8];
    float4 v3 = *(const float4*)&x[idx + 12];
    uint32_t ph[8], pl[8];
    split2(v0.x, v0.y, ph[0], pl[0]);
    split2(v0.z, v0.w, ph[1], pl[1]);
    split2(v1.x, v1.y, ph[2], pl[2]);
    split2(v1.z, v1.w, ph[3], pl[3]);
    split2(v2.x, v2.y, ph[4], pl[4]);
    split2(v2.z, v2.w, ph[5], pl[5]);
    split2(v3.x, v3.y, ph[6], pl[6]);
    split2(v3.z, v3.w, ph[7], pl[7]);
    *(uint4*)&oh[idx]     = make_uint4(ph[0], ph[4], ph[1], ph[5]);
    *(uint4*)&oh[idx + 8] = make_uint4(ph[2], ph[6], ph[3], ph[7]);
    *(uint4*)&ol[idx]     = make_uint4(pl[0], pl[4], pl[1], pl[5]);
    *(uint4*)&ol[idx + 8] = make_uint4(pl[2], pl[6], pl[3], pl[7]);
}

// ---------------------------------------------------------------------------
// bf16x3 GEMM, pre-split + k-pair-permuted operands, cp.async double-buffered.
// R14: per-product mma sweeps over i (4-way ILP) — no adjacent same-accum
// HMMA chains (asm volatile blocks ptxas reordering; order per accumulator
// unchanged -> bit-identical results).
// ---------------------------------------------------------------------------
#define GP 48                  // bf16 pitch
#define G_ARR 12288            // 128*96 bytes per array per buffer
#define G_BUF 49152            // 4 arrays
#define G_TOTAL 98304          // 96 KB -> 2 CTAs/SM

template <bool ROUND_TF32, bool HAS_BIAS>
__device__ __forceinline__
void gemm_body(const __nv_bfloat16* __restrict__ Ah, const __nv_bfloat16* __restrict__ Al,
               const __nv_bfloat16* __restrict__ Bh, const __nv_bfloat16* __restrict__ Bl,
               const float* __restrict__ bias, float* __restrict__ C,
               int m0, int n0, char* smc, bool write_vt)
{
    const uint32_t sb = smem_u32(smc);
    const int tid = threadIdx.x;
    const int lane = tid & 31;
    const int w = tid >> 5;
    const int wm = w & 1, wn = w >> 1;
    const int r = lane >> 2, cq = lane & 3;

    float c[4][4][4];
#pragma unroll
    for (int i = 0; i < 4; i++)
#pragma unroll
        for (int j = 0; j < 4; j++)
#pragma unroll
            for (int x = 0; x < 4; x++) c[i][j][x] = 0.f;

    auto issue = [&](int kt, int buf) {
        const int k0 = kt * 32;
        const uint32_t base = sb + (buf ? G_BUF : 0);
#pragma unroll
        for (int it = 0; it < 2; it++) {
            const int ch = tid + it * 256;
            const int row = ch >> 2, seg = ch & 3;
            const uint32_t off = row * 96 + seg * 16;
            const size_t ga = (size_t)(m0 + row) * KD + k0 + seg * 8;
            const size_t gb = (size_t)(n0 + row) * KD + k0 + seg * 8;
            cp16(base + off,             Ah + ga);
            cp16(base + G_ARR + off,     Al + ga);
            cp16(base + 2 * G_ARR + off, Bh + gb);
            cp16(base + 3 * G_ARR + off, Bl + gb);
        }
        CP_COMMIT();
    };

    issue(0, 0);

    for (int kt = 0; kt < 16; kt++) {
        if (kt < 15) { issue(kt + 1, (kt + 1) & 1); CP_WAIT1(); }
        else         { CP_WAIT0(); }
        __syncthreads();

        const char* bufp = smc + ((kt & 1) ? G_BUF : 0);
        const __nv_bfloat16* Ahs = (const __nv_bfloat16*)(bufp);
        const __nv_bfloat16* Als = (const __nv_bfloat16*)(bufp + G_ARR);
        const __nv_bfloat16* Bhs = (const __nv_bfloat16*)(bufp + 2 * G_ARR);
        const __nv_bfloat16* Bls = (const __nv_bfloat16*)(bufp + 3 * G_ARR);

#pragma unroll
        for (int ks = 0; ks < 2; ks++) {
            const int kb = ks * 16 + 4 * cq;        // stored bf16 col
            uint32_t ah[4][4], al[4][4];
#pragma unroll
            for (int i = 0; i < 4; i++) {
                const int row = wm * 64 + i * 16 + r;
                uint2 h0 = *(const uint2*)&Ahs[row * GP + kb];         // (a0,a2)
                uint2 h1 = *(const uint2*)&Ahs[(row + 8) * GP + kb];   // (a1,a3)
                ah[i][0] = h0.x; ah[i][1] = h1.x; ah[i][2] = h0.y; ah[i][3] = h1.y;
                uint2 l0 = *(const uint2*)&Als[row * GP + kb];
                uint2 l1 = *(const uint2*)&Als[(row + 8) * GP + kb];
                al[i][0] = l0.x; al[i][1] = l1.x; al[i][2] = l0.y; al[i][3] = l1.y;
            }
#pragma unroll
            for (int j = 0; j < 4; j++) {
                const int n = wn * 32 + j * 8 + r;
                uint2 bh = *(const uint2*)&Bhs[n * GP + kb];           // (b0,b1)
                uint2 bl = *(const uint2*)&Bls[n * GP + kb];
                uint32_t bh2[2] = { bh.x, bh.y };
                uint32_t bl2[2] = { bl.x, bl.y };
                // product sweeps: dependent issues 4 apart (was back-to-back)
#pragma unroll
                for (int i = 0; i < 4; i++) mma_bf16(c[i][j], ah[i], bh2);
#pragma unroll
                for (int i = 0; i < 4; i++) mma_bf16(c[i][j], ah[i], bl2);
#pragma unroll
                for (int i = 0; i < 4; i++) mma_bf16(c[i][j], al[i], bh2);
            }
        }
        __syncthreads();
    }

#pragma unroll
    for (int i = 0; i < 4; i++) {
        const int row = m0 + wm * 64 + i * 16 + r;
#pragma unroll
        for (int j = 0; j < 4; j++) {
            const int col = n0 + wn * 32 + j * 8 + 2 * cq;
            float2 v0 = make_float2(c[i][j][0], c[i][j][1]);
            float2 v1 = make_float2(c[i][j][2], c[i][j][3]);
            if (HAS_BIAS) {
                const float2 bz = *(const float2*)&bias[col];
                v0.x += bz.x; v0.y += bz.y;
                v1.x += bz.x; v1.y += bz.y;
            }
            if (ROUND_TF32) {
                v0.x = to_tf32(v0.x); v0.y = to_tf32(v0.y);
                v1.x = to_tf32(v1.x); v1.y = to_tf32(v1.y);
            }
            if (write_vt) {
                const size_t b0 = ((size_t)(row >> 11) * 512 + col) * 2048;
                const int sq0 = row & 2047;
                C[b0 + sq0]            = v0.x;
                C[b0 + 2048 + sq0]     = v0.y;
                C[b0 + sq0 + 8]        = v1.x;
                C[b0 + 2048 + sq0 + 8] = v1.y;
            } else {
                *(float2*)&C[(size_t)row * ND + col] = v0;
                *(float2*)&C[(size_t)(row + 8) * ND + col] = v1;
            }
        }
    }
}

__global__ __launch_bounds__(256, 2)
void qkv_mma()
{
    extern __shared__ char smc[];
    const int z = blockIdx.z;
    const __nv_bfloat16* Ah = g_Xh + (size_t)z * MROWS * ND;
    const __nv_bfloat16* Al = g_Xl + (size_t)z * MROWS * ND;
    const __nv_bfloat16* Bh = g_WTh + (size_t)z * KD * ND;
    const __nv_bfloat16* Bl = g_WTl + (size_t)z * KD * ND;
    float* C = (z == 0) ? g_Q : (z == 1) ? g_K : g_V;
    gemm_body<true, false>(Ah, Al, Bh, Bl, nullptr, C,
                           blockIdx.y * 128, blockIdx.x * 128, smc, z == 2);
}

__global__ __launch_bounds__(256, 2)
void out_mma(const float* __restrict__ bias, float* __restrict__ C)
{
    extern __shared__ char smc[];
    gemm_body<false, true>(g_ATTh, g_ATTl,
                           g_WTh + (size_t)3 * KD * ND, g_WTl + (size_t)3 * KD * ND,
                           bias, C, blockIdx.y * 128, blockIdx.x * 128, smc, false);
}

// ---------------------------------------------------------------------------
// Flash attention — 128 threads / 64 queries per CTA, 4 CTAs/SM. (R12/R13)
// ---------------------------------------------------------------------------
#define AQ_PITCH 68
#define AK_PITCH 72
#define AVT_PITCH 72
#define A_QS 0
#define A_KS 4352                     // 64*68
#define A_VS (4352 + 4608)            // + 64*72
#define A_TOT_FLOATS (A_VS + 4608)    // = 13568 floats = 54272 B -> 4 CTAs/SM

__global__ __launch_bounds__(128, 4)
void attn_mma(const float* __restrict__ Q, const float* __restrict__ K,
              const float* __restrict__ VT)
{
    extern __shared__ float sm[];
    const uint32_t sb = smem_u32(sm);
    float* Qs = sm + A_QS;
    float* Ks = sm + A_KS;
    float* Vt = sm + A_VS;

    const int tid = threadIdx.x;
    const int lane = tid & 31;
    const int wq = tid >> 5;
    const int r = lane >> 2, cq = lane & 3;

    const int bh = blockIdx.y;
    const int b = bh >> 3, h = bh & 7;
    const int q0 = blockIdx.x * 64;

    const float* Qb = Q + (size_t)(b * S1C + q0) * ND + h * 64;
    const float* Kb = K + (size_t)(b * S2C) * ND + h * 64;
    const float* VbT = VT + ((size_t)b * 512 + h * 64) * 2048;

    auto issueK = [&](int kt) {
#pragma unroll
        for (int it = 0; it < 8; it++) {
            const int ch = tid + it * 128;
            const int row = ch >> 4, seg = ch & 15;
            cp16(sb + A_KS * 4 + row * (AK_PITCH * 4) + seg * 16,
                 Kb + (size_t)(kt * 64 + row) * ND + seg * 4);
        }
        CP_COMMIT();
    };
    auto issueV = [&](int kt) {
#pragma unroll
        for (int it = 0; it < 8; it++) {
            const int ch = tid + it * 128;
            const int row = ch >> 4, seg = ch & 15;
            cp16(sb + A_VS * 4 + row * (AVT_PITCH * 4) + seg * 16,
                 VbT + (size_t)row * 2048 + kt * 64 + seg * 4);
        }
        CP_COMMIT();
    };

    // stage Q
#pragma unroll
    for (int it = 0; it < 8; it++) {
        const int ch = tid + it * 128;
        const int row = ch >> 4, seg = ch & 15;
        cp16(sb + A_QS * 4 + row * (AQ_PITCH * 4) + seg * 16,
             Qb + (size_t)row * ND + seg * 4);
    }
    CP_COMMIT();
    issueK(0);

    CP_WAIT0();
    __syncthreads();
    const int prow0 = wq * 16 + r;
    uint32_t qa[8][4];
#pragma unroll
    for (int kf = 0; kf < 8; kf++) {
        const int col = kf * 8 + 2 * cq;
        float2 lo = *(const float2*)&Qs[prow0 * AQ_PITCH + col];
        float2 hi = *(const float2*)&Qs[(prow0 + 8) * AQ_PITCH + col];
        qa[kf][0] = __float_as_uint(lo.x);
        qa[kf][1] = __float_as_uint(hi.x);
        qa[kf][2] = __float_as_uint(lo.y);
        qa[kf][3] = __float_as_uint(hi.y);
    }

    float o[8][4];
#pragma unroll
    for (int j = 0; j < 8; j++)
#pragma unroll
        for (int x = 0; x < 4; x++) o[j][x] = 0.f;
    float sum0 = 0.f, sum1 = 0.f;

    for (int kt = 0; kt < S2C / 64; kt++) {
        CP_WAIT0();
        __syncthreads();

        issueV(kt);          // overlaps QK(t)

        float s8[8][4];
#pragma unroll
        for (int j = 0; j < 8; j++)
#pragma unroll
            for (int x = 0; x < 4; x++) s8[j][x] = 0.f;

#pragma unroll
        for (int kf = 0; kf < 8; kf++) {
            const int col = kf * 8 + 2 * cq;
#pragma unroll
            for (int j = 0; j < 8; j++) {
                float2 kv = *(const float2*)&Ks[(j * 8 + r) * AK_PITCH + col];
                uint32_t kb2[2] = { __float_as_uint(kv.x),
                                    __float_as_uint(kv.y) };
                mma_tf32(s8[j], qa[kf], kb2);
            }
        }

#pragma unroll
        for (int j = 0; j < 8; j++) {
            s8[j][0] = __expf(s8[j][0]);
            s8[j][1] = __expf(s8[j][1]);
            s8[j][2] = __expf(s8[j][2]);
            s8[j][3] = __expf(s8[j][3]);
            sum0 += s8[j][0] + s8[j][1];
            sum1 += s8[j][2] + s8[j][3];
        }

        CP_WAIT0();          // V(t) complete
        __syncthreads();

        if (kt < S2C / 64 - 1) issueK(kt + 1);   // overlaps PV(t)

        // O += P @ V : P from S accumulator; V fragment = one LDS.64
#pragma unroll
        for (int jk = 0; jk < 8; jk++) {
            uint32_t pa[4];
            pa[0] = __float_as_uint(to_tf32(s8[jk][0]));
            pa[1] = __float_as_uint(to_tf32(s8[jk][2]));
            pa[2] = __float_as_uint(to_tf32(s8[jk][1]));
            pa[3] = __float_as_uint(to_tf32(s8[jk][3]));
#pragma unroll
            for (int jd = 0; jd < 8; jd++) {
                float2 vv = *(const float2*)&Vt[(jd * 8 + r) * AVT_PITCH + jk * 8 + 2 * cq];
                uint32_t vb2[2] = { __float_as_uint(vv.x),
                                    __float_as_uint(vv.y) };
                mma_tf32(o[jd], pa, vb2);
            }
        }
    }

    sum0 += __shfl_xor_sync(0xffffffffu, sum0, 1);
    sum0 += __shfl_xor_sync(0xffffffffu, sum0, 2);
    sum1 += __shfl_xor_sync(0xffffffffu, sum1, 1);
    sum1 += __shfl_xor_sync(0xffffffffu, sum1, 2);
    const float rl0 = 1.0f / sum0, rl1 = 1.0f / sum1;

    // write output as bf16 hi/lo at k-permuted columns (feeds out_mma)
    const int grow = b * S1C + q0 + wq * 16 + r;
#pragma unroll
    for (int j = 0; j < 8; j++) {
        const int scol = h * 64 + (j >> 1) * 16 + 4 * cq + 2 * (j & 1);
        uint32_t h0, l0, h1, l1;
        split2(o[j][0] * rl0, o[j][1] * rl0, h0, l0);
        split2(o[j][2] * rl1, o[j][3] * rl1, h1, l1);
        *(uint32_t*)&g_ATTh[(size_t)grow * ND + scol] = h0;
        *(uint32_t*)&g_ATTl[(size_t)grow * ND + scol] = l0;
        *(uint32_t*)&g_ATTh[(size_t)(grow + 8) * ND + scol] = h1;
        *(uint32_t*)&g_ATTl[(size_t)(grow + 8) * ND + scol] = l1;
    }
}

// ---------------------------------------------------------------------------
// Launch
// ---------------------------------------------------------------------------
extern "C" void kernel_launch(void* const* d_in, const int* in_sizes, int n_in,
                              void* d_out, int out_size)
{
    (void)in_sizes; (void)n_in; (void)out_size;
    const float* x1 = (const float*)d_in[0];
    const float* x2 = (const float*)d_in[1];
    const float* x3 = (const float*)d_in[2];
    const float* Wq = (const float*)d_in[3];
    const float* Wk = (const float*)d_in[4];
    const float* Wv = (const float*)d_in[5];
    const float* Wo = (const float*)d_in[6];
    const float* bo = (const float*)d_in[7];
    float* out = (float*)d_out;

    float *Q, *K, *V;
    cudaGetSymbolAddress((void**)&Q, g_Q);
    cudaGetSymbolAddress((void**)&K, g_K);
    cudaGetSymbolAddress((void**)&V, g_V);

    cudaFuncSetAttribute(qkv_mma, cudaFuncAttributeMaxDynamicSharedMemorySize,
                         G_TOTAL);
    cudaFuncSetAttribute(out_mma, cudaFuncAttributeMaxDynamicSharedMemorySize,
                         G_TOTAL);
    cudaFuncSetAttribute(attn_mma, cudaFuncAttributeMaxDynamicSharedMemorySize,
                         A_TOT_FLOATS * 4);

    prep_w<<<dim3(16, 16, 4), 256>>>(Wq, Wk, Wv, Wo);
    prep_x<<<dim3(MROWS * ND / 4096, 3), 256>>>(x1, x2, x3);

    dim3 gQKV(ND / 128, MROWS / 128, 3);   // (4, 64, 3)
    qkv_mma<<<gQKV, 256, G_TOTAL>>>();

    dim3 gA(S1C / 64, BB * NH);            // (32, 32) — 64-query CTAs
    attn_mma<<<gA, 128, A_TOT_FLOATS * 4>>>(Q, K, V);

    dim3 gO(ND / 128, MROWS / 128);        // (4, 64)
    out_mma<<<gO, 256, G_TOTAL>>>(bo, out);
}

// round 15
// speedup vs baseline: 1.0145x; 1.0145x over previous
#include <cuda_runtime.h>
#include <cuda_bf16.h>
#include <cstdint>

// Problem constants
#define BB 4
#define S1C 2048
#define S2C 2048
#define NH 8
#define MROWS (BB * S1C)    // 8192
#define ND 512
#define KD 512

// Scratch (device globals — no allocation allowed)
__device__ __align__(16) float g_Q [MROWS * ND];
__device__ __align__(16) float g_K [MROWS * ND];
__device__ __align__(16) float g_V [MROWS * ND];   // holds V^T: [B*512+col][2048]
__device__ __align__(16) __nv_bfloat16 g_Xh[3 * (size_t)MROWS * ND];
__device__ __align__(16) __nv_bfloat16 g_Xl[3 * (size_t)MROWS * ND];
__device__ __align__(16) __nv_bfloat16 g_ATTh[(size_t)MROWS * ND];
__device__ __align__(16) __nv_bfloat16 g_ATTl[(size_t)MROWS * ND];
__device__ __align__(16) __nv_bfloat16 g_WTh[4 * (size_t)KD * ND];  // W^T [n][k] hi
__device__ __align__(16) __nv_bfloat16 g_WTl[4 * (size_t)KD * ND];  // W^T [n][k] lo

// ---------------------------------------------------------------------------
// helpers
// ---------------------------------------------------------------------------
__device__ __forceinline__ uint32_t smem_u32(const void* p) {
    uint32_t a;
    asm("{ .reg .u64 t; cvta.to.shared.u64 t, %1; cvt.u32.u64 %0, t; }"
        : "=r"(a) : "l"(p));
    return a;
}

__device__ __forceinline__ void cp16(uint32_t dst, const void* src) {
    asm volatile("cp.async.cg.shared.global [%0], [%1], 16;"
                 :: "r"(dst), "l"(src) : "memory");
}
#define CP_COMMIT() asm volatile("cp.async.commit_group;" ::: "memory")
#define CP_WAIT0()  asm volatile("cp.async.wait_group 0;" ::: "memory")
#define CP_WAIT1()  asm volatile("cp.async.wait_group 1;" ::: "memory")

__device__ __forceinline__ float to_tf32(float x) {
    float y;
    asm("cvt.rna.tf32.f32 %0, %1;" : "=f"(y) : "f"(x));
    return y;
}

__device__ __forceinline__ float ex2_fast(float x) {
    float y;
    asm("ex2.approx.f32 %0, %1;" : "=f"(y) : "f"(x));
    return y;
}

__device__ __forceinline__ void mma_bf16(float* c, const uint32_t* a, const uint32_t* b) {
    asm volatile(
        "mma.sync.aligned.m16n8k16.row.col.f32.bf16.bf16.f32 "
        "{%0,%1,%2,%3}, {%4,%5,%6,%7}, {%8,%9}, {%0,%1,%2,%3};"
        : "+f"(c[0]), "+f"(c[1]), "+f"(c[2]), "+f"(c[3])
        : "r"(a[0]), "r"(a[1]), "r"(a[2]), "r"(a[3]), "r"(b[0]), "r"(b[1]));
}

__device__ __forceinline__ void mma_tf32(float* c, const uint32_t* a, const uint32_t* b) {
    asm volatile(
        "mma.sync.aligned.m16n8k8.row.col.f32.tf32.tf32.f32 "
        "{%0,%1,%2,%3}, {%4,%5,%6,%7}, {%8,%9}, {%0,%1,%2,%3};"
        : "+f"(c[0]), "+f"(c[1]), "+f"(c[2]), "+f"(c[3])
        : "r"(a[0]), "r"(a[1]), "r"(a[2]), "r"(a[3]), "r"(b[0]), "r"(b[1]));
}

__device__ __forceinline__ uint32_t pack2(__nv_bfloat16 a, __nv_bfloat16 b) {
    return (uint32_t)__bfloat16_as_ushort(a) | ((uint32_t)__bfloat16_as_ushort(b) << 16);
}

__device__ __forceinline__ void split2(float x, float y, uint32_t& hi, uint32_t& lo) {
    __nv_bfloat16 h0 = __float2bfloat16(x), h1 = __float2bfloat16(y);
    hi = pack2(h0, h1);
    lo = pack2(__float2bfloat16(x - __bfloat162float(h0)),
               __float2bfloat16(y - __bfloat162float(h1)));
}

// ---------------------------------------------------------------------------
// prep_w: W[k][n] -> W^T [n][k-permuted] bf16 hi/lo.
// Wq scaled by 0.125*log2(e): softmax exp becomes a bare ex2.
// k-permutation within each 16-block: pair order [0,4,1,5,2,6,3,7].
// ---------------------------------------------------------------------------
__global__ __launch_bounds__(256)
void prep_w(const float* __restrict__ Wq, const float* __restrict__ Wk,
            const float* __restrict__ Wv, const float* __restrict__ Wo)
{
    __shared__ float tbuf[32][33];
    const int z = blockIdx.z;
    const float* W = (z == 0) ? Wq : (z == 1) ? Wk : (z == 2) ? Wv : Wo;
    const float scale = (z == 0) ? 0.125f * 1.44269504088896340736f : 1.0f;
    __nv_bfloat16* oh = g_WTh + (size_t)z * KD * ND;
    __nv_bfloat16* ol = g_WTl + (size_t)z * KD * ND;
    const int k0 = blockIdx.x * 32, n0 = blockIdx.y * 32;
    const int lane = threadIdx.x & 31, r = threadIdx.x >> 5;

#pragma unroll
    for (int i = 0; i < 4; i++) {
        const int row = r + i * 8;
        tbuf[row][lane] = W[(size_t)(k0 + row) * ND + n0 + lane];
    }
    __syncthreads();
    const int kst = k0 + (lane & 16) + 4 * ((lane >> 1) & 3)
                  + 2 * ((lane >> 3) & 1) + (lane & 1);
#pragma unroll
    for (int i = 0; i < 4; i++) {
        const int row = r + i * 8;
        const float x = tbuf[lane][row] * scale;
        const __nv_bfloat16 hb = __float2bfloat16(x);
        oh[(size_t)(n0 + row) * KD + kst] = hb;
        ol[(size_t)(n0 + row) * KD + kst] =
            __float2bfloat16(x - __bfloat162float(hb));
    }
}

// ---------------------------------------------------------------------------
// prep_x: split x (fp32) -> bf16 hi/lo with k-pair permutation.
// ---------------------------------------------------------------------------
__global__ __launch_bounds__(256)
void prep_x(const float* __restrict__ x1, const float* __restrict__ x2,
            const float* __restrict__ x3)
{
    const int z = blockIdx.y;
    const float* x = (z == 0) ? x1 : (z == 1) ? x2 : x3;
    __nv_bfloat16* oh = g_Xh + (size_t)z * MROWS * ND;
    __nv_bfloat16* ol = g_Xl + (size_t)z * MROWS * ND;
    const size_t idx = ((size_t)blockIdx.x * 256 + threadIdx.x) * 16;
    float4 v0 = *(const float4*)&x[idx];
    float4 v1 = *(const float4*)&x[idx + 4];
    float4 v2 = *(const float4*)&x[idx + 8];
    float4 v3 = *(const float4*)&x[idx + 12];
    uint32_t ph[8], pl[8];
    split2(v0.x, v0.y, ph[0], pl[0]);
    split2(v0.z, v0.w, ph[1], pl[1]);
    split2(v1.x, v1.y, ph[2], pl[2]);
    split2(v1.z, v1.w, ph[3], pl[3]);
    split2(v2.x, v2.y, ph[4], pl[4]);
    split2(v2.z, v2.w, ph[5], pl[5]);
    split2(v3.x, v3.y, ph[6], pl[6]);
    split2(v3.z, v3.w, ph[7], pl[7]);
    *(uint4*)&oh[idx]     = make_uint4(ph[0], ph[4], ph[1], ph[5]);
    *(uint4*)&oh[idx + 8] = make_uint4(ph[2], ph[6], ph[3], ph[7]);
    *(uint4*)&ol[idx]     = make_uint4(pl[0], pl[4], pl[1], pl[5]);
    *(uint4*)&ol[idx + 8] = make_uint4(pl[2], pl[6], pl[3], pl[7]);
}

// ---------------------------------------------------------------------------
// bf16x3 GEMM (R13 ordering), pre-split + k-pair-permuted, cp.async dbuf.
// ---------------------------------------------------------------------------
#define GP 48                  // bf16 pitch
#define G_ARR 12288            // 128*96 bytes per array per buffer
#define G_BUF 49152            // 4 arrays
#define G_TOTAL 98304          // 96 KB -> 2 CTAs/SM

template <bool ROUND_TF32, bool HAS_BIAS>
__device__ __forceinline__
void gemm_body(const __nv_bfloat16* __restrict__ Ah, const __nv_bfloat16* __restrict__ Al,
               const __nv_bfloat16* __restrict__ Bh, const __nv_bfloat16* __restrict__ Bl,
               const float* __restrict__ bias, float* __restrict__ C,
               int m0, int n0, char* smc, bool write_vt)
{
    const uint32_t sb = smem_u32(smc);
    const int tid = threadIdx.x;
    const int lane = tid & 31;
    const int w = tid >> 5;
    const int wm = w & 1, wn = w >> 1;
    const int r = lane >> 2, cq = lane & 3;

    float c[4][4][4];
#pragma unroll
    for (int i = 0; i < 4; i++)
#pragma unroll
        for (int j = 0; j < 4; j++)
#pragma unroll
            for (int x = 0; x < 4; x++) c[i][j][x] = 0.f;

    auto issue = [&](int kt, int buf) {
        const int k0 = kt * 32;
        const uint32_t base = sb + (buf ? G_BUF : 0);
#pragma unroll
        for (int it = 0; it < 2; it++) {
            const int ch = tid + it * 256;
            const int row = ch >> 2, seg = ch & 3;
            const uint32_t off = row * 96 + seg * 16;
            const size_t ga = (size_t)(m0 + row) * KD + k0 + seg * 8;
            const size_t gb = (size_t)(n0 + row) * KD + k0 + seg * 8;
            cp16(base + off,             Ah + ga);
            cp16(base + G_ARR + off,     Al + ga);
            cp16(base + 2 * G_ARR + off, Bh + gb);
            cp16(base + 3 * G_ARR + off, Bl + gb);
        }
        CP_COMMIT();
    };

    issue(0, 0);

    for (int kt = 0; kt < 16; kt++) {
        if (kt < 15) { issue(kt + 1, (kt + 1) & 1); CP_WAIT1(); }
        else         { CP_WAIT0(); }
        __syncthreads();

        const char* bufp = smc + ((kt & 1) ? G_BUF : 0);
        const __nv_bfloat16* Ahs = (const __nv_bfloat16*)(bufp);
        const __nv_bfloat16* Als = (const __nv_bfloat16*)(bufp + G_ARR);
        const __nv_bfloat16* Bhs = (const __nv_bfloat16*)(bufp + 2 * G_ARR);
        const __nv_bfloat16* Bls = (const __nv_bfloat16*)(bufp + 3 * G_ARR);

#pragma unroll
        for (int ks = 0; ks < 2; ks++) {
            const int kb = ks * 16 + 4 * cq;
            uint32_t ah[4][4], al[4][4];
#pragma unroll
            for (int i = 0; i < 4; i++) {
                const int row = wm * 64 + i * 16 + r;
                uint2 h0 = *(const uint2*)&Ahs[row * GP + kb];
                uint2 h1 = *(const uint2*)&Ahs[(row + 8) * GP + kb];
                ah[i][0] = h0.x; ah[i][1] = h1.x; ah[i][2] = h0.y; ah[i][3] = h1.y;
                uint2 l0 = *(const uint2*)&Als[row * GP + kb];
                uint2 l1 = *(const uint2*)&Als[(row + 8) * GP + kb];
                al[i][0] = l0.x; al[i][1] = l1.x; al[i][2] = l0.y; al[i][3] = l1.y;
            }
#pragma unroll
            for (int j = 0; j < 4; j++) {
                const int n = wn * 32 + j * 8 + r;
                uint2 bh = *(const uint2*)&Bhs[n * GP + kb];
                uint2 bl = *(const uint2*)&Bls[n * GP + kb];
                uint32_t bh2[2] = { bh.x, bh.y };
                uint32_t bl2[2] = { bl.x, bl.y };
#pragma unroll
                for (int i = 0; i < 4; i++) {
                    mma_bf16(c[i][j], ah[i], bh2);
                    mma_bf16(c[i][j], ah[i], bl2);
                    mma_bf16(c[i][j], al[i], bh2);
                }
            }
        }
        __syncthreads();
    }

#pragma unroll
    for (int i = 0; i < 4; i++) {
        const int row = m0 + wm * 64 + i * 16 + r;
#pragma unroll
        for (int j = 0; j < 4; j++) {
            const int col = n0 + wn * 32 + j * 8 + 2 * cq;
            float2 v0 = make_float2(c[i][j][0], c[i][j][1]);
            float2 v1 = make_float2(c[i][j][2], c[i][j][3]);
            if (HAS_BIAS) {
                const float2 bz = *(const float2*)&bias[col];
                v0.x += bz.x; v0.y += bz.y;
                v1.x += bz.x; v1.y += bz.y;
            }
            if (ROUND_TF32) {
                v0.x = to_tf32(v0.x); v0.y = to_tf32(v0.y);
                v1.x = to_tf32(v1.x); v1.y = to_tf32(v1.y);
            }
            if (write_vt) {
                const size_t b0 = ((size_t)(row >> 11) * 512 + col) * 2048;
                const int sq0 = row & 2047;
                C[b0 + sq0]            = v0.x;
                C[b0 + 2048 + sq0]     = v0.y;
                C[b0 + sq0 + 8]        = v1.x;
                C[b0 + 2048 + sq0 + 8] = v1.y;
            } else {
                *(float2*)&C[(size_t)row * ND + col] = v0;
                *(float2*)&C[(size_t)(row + 8) * ND + col] = v1;
            }
        }
    }
}

__global__ __launch_bounds__(256, 2)
void qkv_mma()
{
    extern __shared__ char smc[];
    const int z = blockIdx.z;
    const __nv_bfloat16* Ah = g_Xh + (size_t)z * MROWS * ND;
    const __nv_bfloat16* Al = g_Xl + (size_t)z * MROWS * ND;
    const __nv_bfloat16* Bh = g_WTh + (size_t)z * KD * ND;
    const __nv_bfloat16* Bl = g_WTl + (size_t)z * KD * ND;
    float* C = (z == 0) ? g_Q : (z == 1) ? g_K : g_V;
    gemm_body<true, false>(Ah, Al, Bh, Bl, nullptr, C,
                           blockIdx.y * 128, blockIdx.x * 128, smc, z == 2);
}

__global__ __launch_bounds__(256, 2)
void out_mma(const float* __restrict__ bias, float* __restrict__ C)
{
    extern __shared__ char smc[];
    gemm_body<false, true>(g_ATTh, g_ATTl,
                           g_WTh + (size_t)3 * KD * ND, g_WTl + (size_t)3 * KD * ND,
                           bias, C, blockIdx.y * 128, blockIdx.x * 128, smc, false);
}

// ---------------------------------------------------------------------------
// Flash attention — ONE sync + one wait per tile.
// Q fragments direct from gmem (no Q smem). K double-buffered; V single,
// both loaded as one cp.async group {V(t), K(t+1)} at tile top.
// Softmax via bare ex2 (log2e folded into Wq). 128 thr / 64 q, 4 CTAs/SM.
// ---------------------------------------------------------------------------
#define AK_PITCH 72
#define AVT_PITCH 72
#define A_K0 0
#define A_K1 4608                     // 64*72
#define A_VS 9216
#define A_TOT_FLOATS 13824            // 55296 B -> 4 CTAs/SM

__global__ __launch_bounds__(128, 4)
void attn_mma(const float* __restrict__ Q, const float* __restrict__ K,
              const float* __restrict__ VT)
{
    extern __shared__ float sm[];
    const uint32_t sb = smem_u32(sm);
    float* Vt = sm + A_VS;

    const int tid = threadIdx.x;
    const int lane = tid & 31;
    const int wq = tid >> 5;
    const int r = lane >> 2, cq = lane & 3;

    const int bh = blockIdx.y;
    const int b = bh >> 3, h = bh & 7;
    const int q0 = blockIdx.x * 64;

    const float* Qb = Q + (size_t)(b * S1C + q0) * ND + h * 64;
    const float* Kb = K + (size_t)(b * S2C) * ND + h * 64;
    const float* VbT = VT + ((size_t)b * 512 + h * 64) * 2048;

    auto issueK = [&](int kt, int buf) {
        const uint32_t base = sb + (buf ? A_K1 * 4 : 0);
#pragma unroll
        for (int it = 0; it < 8; it++) {
            const int ch = tid + it * 128;
            const int row = ch >> 4, seg = ch & 15;
            cp16(base + row * (AK_PITCH * 4) + seg * 16,
                 Kb + (size_t)(kt * 64 + row) * ND + seg * 4);
        }
    };
    auto issueV = [&](int kt) {
#pragma unroll
        for (int it = 0; it < 8; it++) {
            const int ch = tid + it * 128;
            const int row = ch >> 4, seg = ch & 15;
            cp16(sb + A_VS * 4 + row * (AVT_PITCH * 4) + seg * 16,
                 VbT + (size_t)row * 2048 + kt * 64 + seg * 4);
        }
    };

    // K(0) first (group G0)
    issueK(0, 0);
    CP_COMMIT();

    // Q fragments directly from gmem (fp32, pre-scaled by 0.125*log2e, tf32)
    const int prow0 = wq * 16 + r;
    uint32_t qa[8][4];
#pragma unroll
    for (int kf = 0; kf < 8; kf++) {
        const int col = kf * 8 + 2 * cq;
        float2 lo = *(const float2*)&Qb[(size_t)prow0 * ND + col];
        float2 hi = *(const float2*)&Qb[(size_t)(prow0 + 8) * ND + col];
        qa[kf][0] = __float_as_uint(lo.x);
        qa[kf][1] = __float_as_uint(hi.x);
        qa[kf][2] = __float_as_uint(lo.y);
        qa[kf][3] = __float_as_uint(hi.y);
    }

    float o[8][4];
#pragma unroll
    for (int j = 0; j < 8; j++)
#pragma unroll
        for (int x = 0; x < 4; x++) o[j][x] = 0.f;
    float sum0 = 0.f, sum1 = 0.f;

    for (int kt = 0; kt < S2C / 64; kt++) {
        __syncthreads();     // all warps done with PV(t-1) (V) and QK(t-1) (old K buf)

        // one merged group: V(t) + K(t+1)
        issueV(kt);
        if (kt < S2C / 64 - 1) issueK(kt + 1, (kt + 1) & 1);
        CP_COMMIT();

        CP_WAIT1();          // K(t) ready (older groups drained)

        const float* Ks = sm + ((kt & 1) ? A_K1 : A_K0);

        float s8[8][4];
#pragma unroll
        for (int j = 0; j < 8; j++)
#pragma unroll
            for (int x = 0; x < 4; x++) s8[j][x] = 0.f;

#pragma unroll
        for (int kf = 0; kf < 8; kf++) {
            const int col = kf * 8 + 2 * cq;
#pragma unroll
            for (int j = 0; j < 8; j++) {
                float2 kv = *(const float2*)&Ks[(j * 8 + r) * AK_PITCH + col];
                uint32_t kb2[2] = { __float_as_uint(kv.x),
                                    __float_as_uint(kv.y) };
                mma_tf32(s8[j], qa[kf], kb2);
            }
        }

        // softmax partials: scores are in log2 units -> bare ex2
#pragma unroll
        for (int j = 0; j < 8; j++) {
            s8[j][0] = ex2_fast(s8[j][0]);
            s8[j][1] = ex2_fast(s8[j][1]);
            s8[j][2] = ex2_fast(s8[j][2]);
            s8[j][3] = ex2_fast(s8[j][3]);
            sum0 += s8[j][0] + s8[j][1];
            sum1 += s8[j][2] + s8[j][3];
        }

        CP_WAIT0();          // V(t) (and K(t+1)) ready

        // O += P @ V : P from S accumulator; V fragment = one LDS.64
#pragma unroll
        for (int jk = 0; jk < 8; jk++) {
            uint32_t pa[4];
            pa[0] = __float_as_uint(to_tf32(s8[jk][0]));
            pa[1] = __float_as_uint(to_tf32(s8[jk][2]));
            pa[2] = __float_as_uint(to_tf32(s8[jk][1]));
            pa[3] = __float_as_uint(to_tf32(s8[jk][3]));
#pragma unroll
            for (int jd = 0; jd < 8; jd++) {
                float2 vv = *(const float2*)&Vt[(jd * 8 + r) * AVT_PITCH + jk * 8 + 2 * cq];
                uint32_t vb2[2] = { __float_as_uint(vv.x),
                                    __float_as_uint(vv.y) };
                mma_tf32(o[jd], pa, vb2);
            }
        }
    }

    sum0 += __shfl_xor_sync(0xffffffffu, sum0, 1);
    sum0 += __shfl_xor_sync(0xffffffffu, sum0, 2);
    sum1 += __shfl_xor_sync(0xffffffffu, sum1, 1);
    sum1 += __shfl_xor_sync(0xffffffffu, sum1, 2);
    const float rl0 = 1.0f / sum0, rl1 = 1.0f / sum1;

    // write output as bf16 hi/lo at k-permuted columns (feeds out_mma)
    const int grow = b * S1C + q0 + wq * 16 + r;
#pragma unroll
    for (int j = 0; j < 8; j++) {
        const int scol = h * 64 + (j >> 1) * 16 + 4 * cq + 2 * (j & 1);
        uint32_t h0, l0, h1, l1;
        split2(o[j][0] * rl0, o[j][1] * rl0, h0, l0);
        split2(o[j][2] * rl1, o[j][3] * rl1, h1, l1);
        *(uint32_t*)&g_ATTh[(size_t)grow * ND + scol] = h0;
        *(uint32_t*)&g_ATTl[(size_t)grow * ND + scol] = l0;
        *(uint32_t*)&g_ATTh[(size_t)(grow + 8) * ND + scol] = h1;
        *(uint32_t*)&g_ATTl[(size_t)(grow + 8) * ND + scol] = l1;
    }
}

// ---------------------------------------------------------------------------
// Launch
// ---------------------------------------------------------------------------
extern "C" void kernel_launch(void* const* d_in, const int* in_sizes, int n_in,
                              void* d_out, int out_size)
{
    (void)in_sizes; (void)n_in; (void)out_size;
    const float* x1 = (const float*)d_in[0];
    const float* x2 = (const float*)d_in[1];
    const float* x3 = (const float*)d_in[2];
    const float* Wq = (const float*)d_in[3];
    const float* Wk = (const float*)d_in[4];
    const float* Wv = (const float*)d_in[5];
    const float* Wo = (const float*)d_in[6];
    const float* bo = (const float*)d_in[7];
    float* out = (float*)d_out;

    float *Q, *K, *V;
    cudaGetSymbolAddress((void**)&Q, g_Q);
    cudaGetSymbolAddress((void**)&K, g_K);
    cudaGetSymbolAddress((void**)&V, g_V);

    cudaFuncSetAttribute(qkv_mma, cudaFuncAttributeMaxDynamicSharedMemorySize,
                         G_TOTAL);
    cudaFuncSetAttribute(out_mma, cudaFuncAttributeMaxDynamicSharedMemorySize,
                         G_TOTAL);
    cudaFuncSetAttribute(attn_mma, cudaFuncAttributeMaxDynamicSharedMemorySize,
                         A_TOT_FLOATS * 4);

    prep_w<<<dim3(16, 16, 4), 256>>>(Wq, Wk, Wv, Wo);
    prep_x<<<dim3(MROWS * ND / 4096, 3), 256>>>(x1, x2, x3);

    dim3 gQKV(ND / 128, MROWS / 128, 3);   // (4, 64, 3)
    qkv_mma<<<gQKV, 256, G_TOTAL>>>();

    dim3 gA(S1C / 64, BB * NH);            // (32, 32) — 64-query CTAs
    attn_mma<<<gA, 128, A_TOT_FLOATS * 4>>>(Q, K, V);

    dim3 gO(ND / 128, MROWS / 128);        // (4, 64)
    out_mma<<<gO, 256, G_TOTAL>>>(bo, out);
}